// round 13
// baseline (speedup 1.0000x reference)
#include <cuda_runtime.h>
#include <cuda_fp16.h>
#include <cstdint>
#include <math.h>

// ---------------- problem constants ----------------
#define BATCH 32
#define CIN   64
#define HWIN  16384
#define COUT  128
#define HO    126
#define WO    126
#define NGRP  16
#define HP    63
#define WP    63
#define NTILE 63
#define GN_N  (8 * HO * WO)

// W half-tile per tap (64 co): SW128 [co][32 u32] fp16 = 8 KB
#define WHALF_U32 2048
#define WHALF_B   8192

// slab: 514 pos x 32 u32 (SW128) fp16: 65792 B
#define SLAB_B   65792

// smem layout (bytes):
//  [0,512)     bias (128 f)
//  [512,1024)  sRed (64 f)
//  [1024,1536) sRedQ (64 f)
//  [1536,2048) sSgn (128 f)
//  [2048,+16384)  W ping-pong: 2 bufs x 8192 B
//  [18432,+65792) slab
#define SM_W     2048
#define SM_SLAB  18432
#define SMEM_TOTAL 84224

#define NTHREADS 256

// ---------------- helpers ----------------
__device__ __forceinline__ uint32_t smem_u32(const void* p) {
    uint32_t a;
    asm("{ .reg .u64 t; cvta.to.shared.u64 t, %1; cvt.u32.u64 %0, t; }" : "=r"(a) : "l"(p));
    return a;
}
#define CP_ASYNC16(dst_u32, src_ptr) \
    asm volatile("cp.async.cg.shared.global [%0], [%1], 16;" :: "r"(dst_u32), "l"(src_ptr) : "memory")
#define CP_COMMIT() asm volatile("cp.async.commit_group;" ::: "memory")
#define CP_WAIT0()  asm volatile("cp.async.wait_group 0;" ::: "memory")

#define LDMX4(r, addr) \
    asm volatile("ldmatrix.sync.aligned.m8n8.x4.shared.b16 {%0,%1,%2,%3}, [%4];" \
        : "=r"((r)[0]), "=r"((r)[1]), "=r"((r)[2]), "=r"((r)[3]) : "r"(addr))

__device__ __forceinline__ void mma16816(float* c, const uint32_t* a, const uint32_t* b) {
    asm volatile(
        "mma.sync.aligned.m16n8k16.row.col.f32.f16.f16.f32 "
        "{%0,%1,%2,%3}, {%4,%5,%6,%7}, {%8,%9}, {%0,%1,%2,%3};"
        : "+f"(c[0]), "+f"(c[1]), "+f"(c[2]), "+f"(c[3])
        : "r"(a[0]), "r"(a[1]), "r"(a[2]), "r"(a[3]), "r"(b[0]), "r"(b[1]));
}

// ---------------- device scratch ----------------
// per-(b,co,h) width-pair extremes (max if gn_w*scale>=0 else min): [b][co][126][63]
__device__ float g_mw[(size_t)BATCH * COUT * HO * WP];
__device__ __align__(16) uint32_t g_w[9 * 4096];                 // per-tap SW128 fp16 (128 co)
__device__ float g_psum[BATCH * NGRP * NTILE];
__device__ float g_psq [BATCH * NGRP * NTILE];
__device__ float g_mean[BATCH * NGRP];
__device__ float g_rstd[BATCH * NGRP];

// ---------------------------------------------------------------------------
// Prep: conv_w (O,I,3,3) fp32 -> per-tap SW128 [co][k-word] fp16.
// word(co, kw) = co*32 + (kw ^ ((co&7)<<2))
// ---------------------------------------------------------------------------
__global__ void prep_kernel(const float* __restrict__ conv_w) {
    int idx = blockIdx.x * 256 + threadIdx.x;
    if (idx >= 9 * COUT * CIN) return;
    int r   = idx / (COUT * CIN);
    int rem = idx - r * (COUT * CIN);
    int co  = rem >> 6;
    int ci  = rem & 63;
    float w = conv_w[(co * CIN + ci) * 9 + r];
    __half h = __float2half_rn(w);
    uint32_t word = (uint32_t)(co * 32) + (((uint32_t)ci >> 1) ^ (uint32_t)((co & 7) << 2));
    unsigned short* gw = (unsigned short*)g_w;
    gw[(r * 4096 + word) * 2 + (ci & 1)] = *(unsigned short*)&h;
}

// ---------------------------------------------------------------------------
// Conv via mma.sync m16n8k16 fp16 (single pass), fp32 acc.
// CTA = (row-pair i, N-half, batch b): M=256 pos x N=64 co x K=576.
// 256 threads, 8 warps: 8(M) x 1(N); warp tile 32x64. 2 CTAs/SM.
// W per-tap ping-pong via cp.async; co-resident CTA hides sync bubbles.
// Epilogue: bias, GN partials, width-pair extreme -> g_mw (pool folded).
// ---------------------------------------------------------------------------
__global__ __launch_bounds__(NTHREADS, 2)
void conv_kernel(const float* __restrict__ x, const float* __restrict__ conv_b,
                 const float* __restrict__ gn_w, const float* __restrict__ scale) {
    extern __shared__ char smem[];
    float*    sBias  = (float*)smem;
    float*    sRed   = (float*)(smem + 512);
    float*    sRedQ  = (float*)(smem + 1024);
    float*    sSgn   = (float*)(smem + 1536);
    uint32_t* sW     = (uint32_t*)(smem + SM_W);

    const int t    = threadIdx.x;
    const int wid  = t >> 5;
    const int lane = t & 31;
    const int g    = lane >> 2;
    const int tl   = lane & 3;
    const int li   = lane & 7;           // ldmatrix row-within-octet
    const int lsel = lane >> 3;          // ldmatrix matrix selector (0..3)
    const int wm   = wid;                // M warp index (0..7)
    const int warp_m = wm * 32;
    const int i     = blockIdx.x;        // row pair: output rows 2i, 2i+1
    const int nhalf = blockIdx.y;        // 0: co 0..63, 1: co 64..127
    const int b     = blockIdx.z;
    const int cbase = nhalf * 64;
    const int p0 = i * 256;

    const uint32_t sW_addr = smem_u32(sW);
    const uint32_t slab_a  = smem_u32(smem + SM_SLAB);

    // prefetch W tap 0 (this N-half) -> buf 0
    {
        const char* src = (const char*)(g_w + nhalf * WHALF_U32);
        for (int j = t; j < WHALF_B / 16; j += NTHREADS)
            CP_ASYNC16(sW_addr + j * 16, src + j * 16);
        CP_COMMIT();
    }
    if (t < COUT) {
        sBias[t] = conv_b[t];
        sSgn[t]  = gn_w[t] * scale[t];
    }

    // ---- build x slab: 514 pos x 64 ci, fp16, SW128 [pos][k-word] ----
    {
        const float* xb = x + (size_t)b * CIN * HWIN;
        unsigned short* sh = (unsigned short*)(smem + SM_SLAB);
        for (int idx = t; idx < CIN * 129; idx += NTHREADS) {
            int ci   = idx / 129;
            int gi   = idx - ci * 129;
            int pos0 = gi * 4;
            float v[4];
            if (pos0 + 3 < 514 && p0 + pos0 + 4 <= HWIN) {
                float4 f = *(const float4*)(xb + (size_t)ci * HWIN + p0 + pos0);
                v[0] = f.x; v[1] = f.y; v[2] = f.z; v[3] = f.w;
            } else {
#pragma unroll
                for (int e = 0; e < 4; e++) {
                    int pos = pos0 + e;
                    v[e] = (pos < 514 && p0 + pos < HWIN)
                         ? xb[(size_t)ci * HWIN + p0 + pos] : 0.f;
                }
            }
#pragma unroll
            for (int e = 0; e < 4; e++) {
                int pos = pos0 + e;
                if (pos >= 514) break;
                __half h = __float2half_rn(v[e]);
                uint32_t word = (uint32_t)(pos * 32) +
                                (((uint32_t)ci >> 1) ^ (uint32_t)((pos & 7) << 2));
                sh[word * 2 + (ci & 1)] = *(unsigned short*)&h;
            }
        }
    }
    CP_WAIT0();
    __syncthreads();

    // B ldmatrix per-lane row constants (co local to this N-half)
    uint32_t bRow[4]; int bKey[4];
#pragma unroll
    for (int np = 0; np < 4; np++) {
        int col = ((2 * np + (lsel >> 1)) << 3) + li;     // 0..63
        bRow[np] = (uint32_t)(col * 128);
        bKey[np] = (col & 7) << 2;
    }
    const int bCh = (lsel & 1) << 2;     // chunk word add for B selector
    const int aCh = (lsel >> 1) << 2;    // chunk word add for A selector

    float acc[2][8][4];
#pragma unroll
    for (int m = 0; m < 2; m++)
#pragma unroll
        for (int n = 0; n < 8; n++)
#pragma unroll
            for (int e = 0; e < 4; e++) acc[m][n][e] = 0.f;

    for (int tap = 0; tap < 9; tap++) {
        const int buf = tap & 1;
        if (tap < 8) {   // prefetch next tap into other buffer (safe: synced)
            const char* src = (const char*)(g_w + (tap + 1) * 4096 + nhalf * WHALF_U32);
            const uint32_t dst = sW_addr + (buf ^ 1) * WHALF_B;
            for (int j = t; j < WHALF_B / 16; j += NTHREADS)
                CP_ASYNC16(dst + j * 16, src + j * 16);
            CP_COMMIT();
        }
        const uint32_t WH_a = sW_addr + buf * WHALF_B;

        const int offp = (tap / 3) * 128 + (tap % 3);
        uint32_t aBase[2]; int aKey[2];
#pragma unroll
        for (int m = 0; m < 2; m++) {
            int row = offp + warp_m + m * 16 + ((lsel & 1) << 3) + li;
            aBase[m] = slab_a + (uint32_t)(row * 128);
            aKey[m]  = (row & 7) << 2;
        }

#pragma unroll
        for (int kc = 0; kc < 4; kc++) {
            const int kwA = kc * 8 + aCh;
            const int kwB = kc * 8 + bCh;
            uint32_t ah[2][4];
#pragma unroll
            for (int m = 0; m < 2; m++)
                LDMX4(ah[m], aBase[m] + (uint32_t)((kwA ^ aKey[m]) << 2));
#pragma unroll
            for (int np = 0; np < 4; np++) {
                const int n0 = 2 * np, n1 = n0 + 1;
                uint32_t bh[4];
                LDMX4(bh, WH_a + bRow[np] + (uint32_t)((kwB ^ bKey[np]) << 2));
#pragma unroll
                for (int m = 0; m < 2; m++) {
                    mma16816(acc[m][n0], ah[m], bh);
                    mma16816(acc[m][n1], ah[m], bh + 2);
                }
            }
        }
        if (tap < 8) CP_WAIT0();
        __syncthreads();
    }

    // ---- epilogue: bias, GN partials, width-pair extremes -> g_mw ----
    const bool gEven = ((g & 1) == 0);
#pragma unroll
    for (int n = 0; n < 8; n++) {
        const int co0 = cbase + n * 8 + tl * 2;
        const int co1 = co0 + 1;
        const float b0 = sBias[co0];
        const float b1 = sBias[co1];
        const bool mx0 = (sSgn[co0] >= 0.f);
        const bool mx1 = (sSgn[co1] >= 0.f);
        float s = 0.f, q = 0.f;
#pragma unroll
        for (int m = 0; m < 2; m++) {
            const int pa = warp_m + m * 16 + g;
            const int pb = pa + 8;
            const int wA = pa & 127, hA = 2 * i + (pa >> 7);
            const int wB = pb & 127;
            float v0 = acc[m][n][0] + b0;
            float v1 = acc[m][n][1] + b1;
            float v2 = acc[m][n][2] + b0;
            float v3 = acc[m][n][3] + b1;
            // exchange with the adjacent-w lane (g ^ 1 -> lane ^ 4)
            float p0v = __shfl_xor_sync(0xffffffffu, v0, 4);
            float p1v = __shfl_xor_sync(0xffffffffu, v1, 4);
            float p2v = __shfl_xor_sync(0xffffffffu, v2, 4);
            float p3v = __shfl_xor_sync(0xffffffffu, v3, 4);
            if (wA < 126) { s += v0 + v1; q += v0 * v0 + v1 * v1; }
            if (wB < 126) { s += v2 + v3; q += v2 * v2 + v3 * v3; }
            if (gEven) {
                const size_t rowBase0 = ((size_t)(b * COUT + co0) * HO + hA) * WP;
                const size_t rowBase1 = ((size_t)(b * COUT + co1) * HO + hA) * WP;
                if (wA < 126) {
                    float e0 = mx0 ? fmaxf(v0, p0v) : fminf(v0, p0v);
                    float e1 = mx1 ? fmaxf(v1, p1v) : fminf(v1, p1v);
                    g_mw[rowBase0 + (wA >> 1)] = e0;
                    g_mw[rowBase1 + (wA >> 1)] = e1;
                }
                if (wB < 126) {
                    float e2 = mx0 ? fmaxf(v2, p2v) : fminf(v2, p2v);
                    float e3 = mx1 ? fmaxf(v3, p3v) : fminf(v3, p3v);
                    g_mw[rowBase0 + (wB >> 1)] = e2;
                    g_mw[rowBase1 + (wB >> 1)] = e3;
                }
            }
        }
#pragma unroll
        for (int o = 16; o > 0; o >>= 1) {
            s += __shfl_xor_sync(0xffffffffu, s, o);
            q += __shfl_xor_sync(0xffffffffu, q, o);
        }
        if (lane == 0) {
            sRed [n * 8 + wm] = s;
            sRedQ[n * 8 + wm] = q;
        }
    }
    __syncthreads();
    if (t < 8) {
        float S = 0.f, Q = 0.f;
#pragma unroll
        for (int k = 0; k < 8; k++) { S += sRed[t * 8 + k]; Q += sRedQ[t * 8 + k]; }
        const int grp = nhalf * 8 + t;
        g_psum[(b * NGRP + grp) * NTILE + i] = S;
        g_psq [(b * NGRP + grp) * NTILE + i] = Q;
    }
}

// ---------------------------------------------------------------------------
__global__ void stats_kernel() {
    int i = blockIdx.x * blockDim.x + threadIdx.x;
    if (i < BATCH * NGRP) {
        float s = 0.f, q = 0.f;
        const float* ps = g_psum + i * NTILE;
        const float* pq = g_psq  + i * NTILE;
        for (int tl = 0; tl < NTILE; tl++) { s += ps[tl]; q += pq[tl]; }
        const float invN = 1.f / (float)GN_N;
        float mean = s * invN;
        float var  = q * invN - mean * mean;
        g_mean[i] = mean;
        g_rstd[i] = rsqrtf(var + 1e-5f);
    }
}

// ---------------------------------------------------------------------------
// Pool: read 2 width-pair extremes (rows 2oh, 2oh+1), affine, max, clamp.
// ---------------------------------------------------------------------------
__global__ void pool_kernel(const float* __restrict__ gn_w,
                            const float* __restrict__ gn_b,
                            const float* __restrict__ scale,
                            float* __restrict__ out) {
    int idx = blockIdx.x * blockDim.x + threadIdx.x;
    if (idx >= BATCH * COUT * HP * WP) return;
    int ow  = idx % WP;
    int tmp = idx / WP;
    int oh  = tmp % HP;
    tmp    /= HP;
    int c   = tmp % COUT;
    int b   = tmp / COUT;

    const int bg = b * NGRP + (c >> 3);
    const float mean = g_mean[bg];
    const float rstd = g_rstd[bg];
    const float a  = rstd * gn_w[c] * scale[c];
    const float bb = (gn_b[c] - mean * rstd * gn_w[c]) * scale[c];

    const float* mp = g_mw + ((size_t)(b * COUT + c) * HO + oh * 2) * (size_t)WP + ow;
    float v0 = fmaf(a, mp[0],  bb);
    float v1 = fmaf(a, mp[WP], bb);
    float m = fmaxf(v0, v1);
    out[idx] = fminf(fmaxf(m, 0.0f), 1.0f);
}

// ---------------------------------------------------------------------------
extern "C" void kernel_launch(void* const* d_in, const int* in_sizes, int n_in,
                              void* d_out, int out_size) {
    const float* x      = (const float*)d_in[0];
    const float* conv_w = (const float*)d_in[1];
    const float* conv_b = (const float*)d_in[2];
    const float* gn_w   = (const float*)d_in[3];
    const float* gn_b   = (const float*)d_in[4];
    const float* scale  = (const float*)d_in[5];
    float* out = (float*)d_out;

    cudaFuncSetAttribute(conv_kernel, cudaFuncAttributeMaxDynamicSharedMemorySize, SMEM_TOTAL);

    prep_kernel<<<(9 * COUT * CIN + 255) / 256, 256>>>(conv_w);
    conv_kernel<<<dim3(NTILE, 2, BATCH), NTHREADS, SMEM_TOTAL>>>(x, conv_b, gn_w, scale);
    stats_kernel<<<2, 256>>>();
    const int npool = BATCH * COUT * HP * WP;
    pool_kernel<<<(npool + 255) / 256, 256>>>(gn_w, gn_b, scale, out);
}

// round 14
// speedup vs baseline: 1.0845x; 1.0845x over previous
#include <cuda_runtime.h>
#include <cuda_fp16.h>
#include <cstdint>
#include <math.h>

// ---------------- problem constants ----------------
#define BATCH 32
#define CIN   64
#define HWIN  16384
#define COUT  128
#define HO    126
#define WO    126
#define NGRP  16
#define HP    63
#define WP    63
#define NROW  126                       // GN partial tiles = output rows
#define GN_N  (8 * HO * WO)

// W tile per tap (128 co): SW128 [co][32 u32] fp16 = 16 KB
#define WTAP_U32 4096
#define WTAP_B   16384

// slab: 386 pos x 32 u32 (SW128) fp16 = 49408 B
#define SLAB_POS 386
#define SLAB_B   49408

// smem layout (bytes):
//  [0,512)     bias (128 f)
//  [512,1024)  sRed (64 f)
//  [1024,1536) sRedQ (64 f)
//  [1536,2048) sSgn (128 f)
//  [2048,+32768)  W ping-pong: 2 bufs x 16384 B
//  [34816,+49408) slab
#define SM_W     2048
#define SM_SLAB  34816
#define SMEM_TOTAL 84224

#define NTHREADS 256

// ---------------- helpers ----------------
__device__ __forceinline__ uint32_t smem_u32(const void* p) {
    uint32_t a;
    asm("{ .reg .u64 t; cvta.to.shared.u64 t, %1; cvt.u32.u64 %0, t; }" : "=r"(a) : "l"(p));
    return a;
}
#define CP_ASYNC16(dst_u32, src_ptr) \
    asm volatile("cp.async.cg.shared.global [%0], [%1], 16;" :: "r"(dst_u32), "l"(src_ptr) : "memory")
#define CP_COMMIT() asm volatile("cp.async.commit_group;" ::: "memory")
#define CP_WAIT0()  asm volatile("cp.async.wait_group 0;" ::: "memory")

#define LDMX4(r, addr) \
    asm volatile("ldmatrix.sync.aligned.m8n8.x4.shared.b16 {%0,%1,%2,%3}, [%4];" \
        : "=r"((r)[0]), "=r"((r)[1]), "=r"((r)[2]), "=r"((r)[3]) : "r"(addr))

__device__ __forceinline__ void mma16816(float* c, const uint32_t* a, const uint32_t* b) {
    asm volatile(
        "mma.sync.aligned.m16n8k16.row.col.f32.f16.f16.f32 "
        "{%0,%1,%2,%3}, {%4,%5,%6,%7}, {%8,%9}, {%0,%1,%2,%3};"
        : "+f"(c[0]), "+f"(c[1]), "+f"(c[2]), "+f"(c[3])
        : "r"(a[0]), "r"(a[1]), "r"(a[2]), "r"(a[3]), "r"(b[0]), "r"(b[1]));
}

// ---------------- device scratch ----------------
// per-(b,co,h) width-pair extremes (max if gn_w*scale>=0 else min): [b][co][126][63]
__device__ float g_mw[(size_t)BATCH * COUT * HO * WP];
__device__ __align__(16) uint32_t g_w[9 * WTAP_U32];             // per-tap SW128 fp16
__device__ float g_psum[BATCH * NGRP * NROW];
__device__ float g_psq [BATCH * NGRP * NROW];
__device__ float g_mean[BATCH * NGRP];
__device__ float g_rstd[BATCH * NGRP];

// ---------------------------------------------------------------------------
// Prep: conv_w (O,I,3,3) fp32 -> per-tap SW128 [co][k-word] fp16.
// word(co, kw) = co*32 + (kw ^ ((co&7)<<2))
// ---------------------------------------------------------------------------
__global__ void prep_kernel(const float* __restrict__ conv_w) {
    int idx = blockIdx.x * 256 + threadIdx.x;
    if (idx >= 9 * COUT * CIN) return;
    int r   = idx / (COUT * CIN);
    int rem = idx - r * (COUT * CIN);
    int co  = rem >> 6;
    int ci  = rem & 63;
    float w = conv_w[(co * CIN + ci) * 9 + r];
    __half h = __float2half_rn(w);
    uint32_t word = (uint32_t)(co * 32) + (((uint32_t)ci >> 1) ^ (uint32_t)((co & 7) << 2));
    unsigned short* gw = (unsigned short*)g_w;
    gw[(r * WTAP_U32 + word) * 2 + (ci & 1)] = *(unsigned short*)&h;
}

// ---------------------------------------------------------------------------
// Conv via mma.sync m16n8k16 fp16 (single pass), fp32 acc.
// CTA = (output row h, batch b): M=128 pos x N=128 co x K=576.
// 256 threads, 8 warps: 4(M) x 2(N); warp tile 32x64. 2 CTAs/SM.
// Co-resident CTA hides slab-build/sync/epilogue bubbles.
// Epilogue: bias, GN partials, width-pair extreme -> g_mw (pool folded).
// ---------------------------------------------------------------------------
__global__ __launch_bounds__(NTHREADS, 2)
void conv_kernel(const float* __restrict__ x, const float* __restrict__ conv_b,
                 const float* __restrict__ gn_w, const float* __restrict__ scale) {
    extern __shared__ char smem[];
    float*    sBias  = (float*)smem;
    float*    sRed   = (float*)(smem + 512);
    float*    sRedQ  = (float*)(smem + 1024);
    float*    sSgn   = (float*)(smem + 1536);
    uint32_t* sW     = (uint32_t*)(smem + SM_W);

    const int t    = threadIdx.x;
    const int wid  = t >> 5;
    const int lane = t & 31;
    const int g    = lane >> 2;
    const int tl   = lane & 3;
    const int li   = lane & 7;           // ldmatrix row-within-octet
    const int lsel = lane >> 3;          // ldmatrix matrix selector (0..3)
    const int wm   = wid & 3;            // M warp index (0..3)
    const int wn   = wid >> 2;           // N warp index (0..1)
    const int warp_m = wm * 32;
    const int warp_n = wn * 64;
    const int h  = blockIdx.x;           // output row 0..125
    const int b  = blockIdx.y;
    const int p0 = h * 128;              // flat base position

    const uint32_t sW_addr = smem_u32(sW);
    const uint32_t slab_a  = smem_u32(smem + SM_SLAB);

    // prefetch W tap 0 -> buf 0
    {
        const char* src = (const char*)g_w;
        for (int j = t; j < WTAP_B / 16; j += NTHREADS)
            CP_ASYNC16(sW_addr + j * 16, src + j * 16);
        CP_COMMIT();
    }
    if (t < COUT) {
        sBias[t] = conv_b[t];
        sSgn[t]  = gn_w[t] * scale[t];
    }

    // ---- build x slab: 386 pos x 64 ci, fp16, SW128 [pos][k-word] ----
    {
        const float* xb = x + (size_t)b * CIN * HWIN;
        unsigned short* sh = (unsigned short*)(smem + SM_SLAB);
        for (int idx = t; idx < CIN * 97; idx += NTHREADS) {
            int ci   = idx / 97;
            int gi   = idx - ci * 97;
            int pos0 = gi * 4;
            float v[4];
            if (pos0 + 3 < SLAB_POS && p0 + pos0 + 4 <= HWIN) {
                float4 f = *(const float4*)(xb + (size_t)ci * HWIN + p0 + pos0);
                v[0] = f.x; v[1] = f.y; v[2] = f.z; v[3] = f.w;
            } else {
#pragma unroll
                for (int e = 0; e < 4; e++) {
                    int pos = pos0 + e;
                    v[e] = (pos < SLAB_POS && p0 + pos < HWIN)
                         ? xb[(size_t)ci * HWIN + p0 + pos] : 0.f;
                }
            }
#pragma unroll
            for (int e = 0; e < 4; e++) {
                int pos = pos0 + e;
                if (pos >= SLAB_POS) break;
                __half hv = __float2half_rn(v[e]);
                uint32_t word = (uint32_t)(pos * 32) +
                                (((uint32_t)ci >> 1) ^ (uint32_t)((pos & 7) << 2));
                sh[word * 2 + (ci & 1)] = *(unsigned short*)&hv;
            }
        }
    }
    CP_WAIT0();
    __syncthreads();

    // B ldmatrix per-lane row constants
    uint32_t bRow[4]; int bKey[4];
#pragma unroll
    for (int np = 0; np < 4; np++) {
        int co = warp_n + ((2 * np + (lsel >> 1)) << 3) + li;
        bRow[np] = (uint32_t)(co * 128);
        bKey[np] = (co & 7) << 2;
    }
    const int bCh = (lsel & 1) << 2;     // chunk word add for B selector
    const int aCh = (lsel >> 1) << 2;    // chunk word add for A selector

    float acc[2][8][4];
#pragma unroll
    for (int m = 0; m < 2; m++)
#pragma unroll
        for (int n = 0; n < 8; n++)
#pragma unroll
            for (int e = 0; e < 4; e++) acc[m][n][e] = 0.f;

    for (int tap = 0; tap < 9; tap++) {
        const int buf = tap & 1;
        if (tap < 8) {   // prefetch next tap into other buffer (safe: synced)
            const char* src = (const char*)(g_w + (tap + 1) * WTAP_U32);
            const uint32_t dst = sW_addr + (buf ^ 1) * WTAP_B;
            for (int j = t; j < WTAP_B / 16; j += NTHREADS)
                CP_ASYNC16(dst + j * 16, src + j * 16);
            CP_COMMIT();
        }
        const uint32_t WH_a = sW_addr + buf * WTAP_B;

        const int offp = (tap / 3) * 128 + (tap % 3);
        uint32_t aBase[2]; int aKey[2];
#pragma unroll
        for (int m = 0; m < 2; m++) {
            int row = offp + warp_m + m * 16 + ((lsel & 1) << 3) + li;
            aBase[m] = slab_a + (uint32_t)(row * 128);
            aKey[m]  = (row & 7) << 2;
        }

#pragma unroll
        for (int kc = 0; kc < 4; kc++) {
            const int kwA = kc * 8 + aCh;
            const int kwB = kc * 8 + bCh;
            uint32_t ah[2][4];
#pragma unroll
            for (int m = 0; m < 2; m++)
                LDMX4(ah[m], aBase[m] + (uint32_t)((kwA ^ aKey[m]) << 2));
#pragma unroll
            for (int np = 0; np < 4; np++) {
                const int n0 = 2 * np, n1 = n0 + 1;
                uint32_t bh[4];
                LDMX4(bh, WH_a + bRow[np] + (uint32_t)((kwB ^ bKey[np]) << 2));
#pragma unroll
                for (int m = 0; m < 2; m++) {
                    mma16816(acc[m][n0], ah[m], bh);
                    mma16816(acc[m][n1], ah[m], bh + 2);
                }
            }
        }
        if (tap < 8) CP_WAIT0();
        __syncthreads();
    }

    // ---- epilogue: bias, GN partials, width-pair extremes -> g_mw ----
    const bool gEven = ((g & 1) == 0);
#pragma unroll
    for (int n = 0; n < 8; n++) {
        const int co0 = warp_n + n * 8 + tl * 2;
        const int co1 = co0 + 1;
        const float b0 = sBias[co0];
        const float b1 = sBias[co1];
        const bool mx0 = (sSgn[co0] >= 0.f);
        const bool mx1 = (sSgn[co1] >= 0.f);
        float s = 0.f, q = 0.f;
#pragma unroll
        for (int m = 0; m < 2; m++) {
            const int wA = warp_m + m * 16 + g;     // 0..127 (width)
            const int wB = wA + 8;
            float v0 = acc[m][n][0] + b0;
            float v1 = acc[m][n][1] + b1;
            float v2 = acc[m][n][2] + b0;
            float v3 = acc[m][n][3] + b1;
            // exchange with the adjacent-w lane (g ^ 1 -> lane ^ 4)
            float p0v = __shfl_xor_sync(0xffffffffu, v0, 4);
            float p1v = __shfl_xor_sync(0xffffffffu, v1, 4);
            float p2v = __shfl_xor_sync(0xffffffffu, v2, 4);
            float p3v = __shfl_xor_sync(0xffffffffu, v3, 4);
            if (wA < 126) { s += v0 + v1; q += v0 * v0 + v1 * v1; }
            if (wB < 126) { s += v2 + v3; q += v2 * v2 + v3 * v3; }
            if (gEven) {
                const size_t rowBase0 = ((size_t)(b * COUT + co0) * HO + h) * WP;
                const size_t rowBase1 = ((size_t)(b * COUT + co1) * HO + h) * WP;
                if (wA < 126) {
                    float e0 = mx0 ? fmaxf(v0, p0v) : fminf(v0, p0v);
                    float e1 = mx1 ? fmaxf(v1, p1v) : fminf(v1, p1v);
                    g_mw[rowBase0 + (wA >> 1)] = e0;
                    g_mw[rowBase1 + (wA >> 1)] = e1;
                }
                if (wB < 126) {
                    float e2 = mx0 ? fmaxf(v2, p2v) : fminf(v2, p2v);
                    float e3 = mx1 ? fmaxf(v3, p3v) : fminf(v3, p3v);
                    g_mw[rowBase0 + (wB >> 1)] = e2;
                    g_mw[rowBase1 + (wB >> 1)] = e3;
                }
            }
        }
#pragma unroll
        for (int o = 16; o > 0; o >>= 1) {
            s += __shfl_xor_sync(0xffffffffu, s, o);
            q += __shfl_xor_sync(0xffffffffu, q, o);
        }
        if (lane == 0) {
            sRed [(wn * 8 + n) * 4 + wm] = s;
            sRedQ[(wn * 8 + n) * 4 + wm] = q;
        }
    }
    __syncthreads();
    if (t < 16) {
        float S = 0.f, Q = 0.f;
#pragma unroll
        for (int k = 0; k < 4; k++) { S += sRed[t * 4 + k]; Q += sRedQ[t * 4 + k]; }
        g_psum[(b * NGRP + t) * NROW + h] = S;
        g_psq [(b * NGRP + t) * NROW + h] = Q;
    }
}

// ---------------------------------------------------------------------------
__global__ void stats_kernel() {
    int i = blockIdx.x * blockDim.x + threadIdx.x;
    if (i < BATCH * NGRP) {
        float s = 0.f, q = 0.f;
        const float* ps = g_psum + i * NROW;
        const float* pq = g_psq  + i * NROW;
        for (int tl = 0; tl < NROW; tl++) { s += ps[tl]; q += pq[tl]; }
        const float invN = 1.f / (float)GN_N;
        float mean = s * invN;
        float var  = q * invN - mean * mean;
        g_mean[i] = mean;
        g_rstd[i] = rsqrtf(var + 1e-5f);
    }
}

// ---------------------------------------------------------------------------
// Pool: read 2 width-pair extremes (rows 2oh, 2oh+1), affine, max, clamp.
// ---------------------------------------------------------------------------
__global__ void pool_kernel(const float* __restrict__ gn_w,
                            const float* __restrict__ gn_b,
                            const float* __restrict__ scale,
                            float* __restrict__ out) {
    int idx = blockIdx.x * blockDim.x + threadIdx.x;
    if (idx >= BATCH * COUT * HP * WP) return;
    int ow  = idx % WP;
    int tmp = idx / WP;
    int oh  = tmp % HP;
    tmp    /= HP;
    int c   = tmp % COUT;
    int b   = tmp / COUT;

    const int bg = b * NGRP + (c >> 3);
    const float mean = g_mean[bg];
    const float rstd = g_rstd[bg];
    const float a  = rstd * gn_w[c] * scale[c];
    const float bb = (gn_b[c] - mean * rstd * gn_w[c]) * scale[c];

    const float* mp = g_mw + ((size_t)(b * COUT + c) * HO + oh * 2) * (size_t)WP + ow;
    float v0 = fmaf(a, mp[0],  bb);
    float v1 = fmaf(a, mp[WP], bb);
    float m = fmaxf(v0, v1);
    out[idx] = fminf(fmaxf(m, 0.0f), 1.0f);
}

// ---------------------------------------------------------------------------
extern "C" void kernel_launch(void* const* d_in, const int* in_sizes, int n_in,
                              void* d_out, int out_size) {
    const float* x      = (const float*)d_in[0];
    const float* conv_w = (const float*)d_in[1];
    const float* conv_b = (const float*)d_in[2];
    const float* gn_w   = (const float*)d_in[3];
    const float* gn_b   = (const float*)d_in[4];
    const float* scale  = (const float*)d_in[5];
    float* out = (float*)d_out;

    cudaFuncSetAttribute(conv_kernel, cudaFuncAttributeMaxDynamicSharedMemorySize, SMEM_TOTAL);

    prep_kernel<<<(9 * COUT * CIN + 255) / 256, 256>>>(conv_w);
    conv_kernel<<<dim3(HO, BATCH), NTHREADS, SMEM_TOTAL>>>(x, conv_b, gn_w, scale);
    stats_kernel<<<2, 256>>>();
    const int npool = BATCH * COUT * HP * WP;
    pool_kernel<<<(npool + 255) / 256, 256>>>(gn_w, gn_b, scale, out);
}

// round 15
// speedup vs baseline: 1.6301x; 1.5032x over previous
#include <cuda_runtime.h>
#include <cuda_fp16.h>
#include <cstdint>
#include <math.h>

// ---------------- problem constants ----------------
#define BATCH 32
#define CIN   64
#define HWIN  16384
#define COUT  128
#define HO    126
#define WO    126
#define NGRP  16
#define HP    63
#define WP    63
#define NTILE 63
#define GN_N  (8 * HO * WO)

// W tile per tap: SW128 layout [co][32 u32] fp16: 4096 u32 = 16 KB; all 9 resident
#define WTAP_U32 4096
#define WTAP_B   16384
#define WALL_B   (9 * WTAP_B)          // 147456

// slab: 514 pos x 32 u32 (SW128) fp16: 65792 B
#define SLAB_B   65792

// pre-swizzled fp16 x: [b][pos][32 u32], padded pitch (rows >=16384 stay zero)
#define XS_PITCH 16512

// smem layout (bytes):
//  [0,512)     bias (128 f)
//  [512,1024)  sRed (128 f)
//  [1024,1536) sRedQ (128 f)
//  [1536,2048) sSgn (128 f)
//  [2048,+147456)  W all taps
//  [149504,+65792) slab
#define SM_W     2048
#define SM_SLAB  149504
#define SMEM_TOTAL 215296

#define NTHREADS 512

// ---------------- helpers ----------------
__device__ __forceinline__ uint32_t smem_u32(const void* p) {
    uint32_t a;
    asm("{ .reg .u64 t; cvta.to.shared.u64 t, %1; cvt.u32.u64 %0, t; }" : "=r"(a) : "l"(p));
    return a;
}
#define CP_ASYNC16(dst_u32, src_ptr) \
    asm volatile("cp.async.cg.shared.global [%0], [%1], 16;" :: "r"(dst_u32), "l"(src_ptr) : "memory")
#define CP_COMMIT() asm volatile("cp.async.commit_group;" ::: "memory")
#define CP_WAIT0()  asm volatile("cp.async.wait_group 0;" ::: "memory")

#define LDMX4(r, addr) \
    asm volatile("ldmatrix.sync.aligned.m8n8.x4.shared.b16 {%0,%1,%2,%3}, [%4];" \
        : "=r"((r)[0]), "=r"((r)[1]), "=r"((r)[2]), "=r"((r)[3]) : "r"(addr))

__device__ __forceinline__ void mma16816(float* c, const uint32_t* a, const uint32_t* b) {
    asm volatile(
        "mma.sync.aligned.m16n8k16.row.col.f32.f16.f16.f32 "
        "{%0,%1,%2,%3}, {%4,%5,%6,%7}, {%8,%9}, {%0,%1,%2,%3};"
        : "+f"(c[0]), "+f"(c[1]), "+f"(c[2]), "+f"(c[3])
        : "r"(a[0]), "r"(a[1]), "r"(a[2]), "r"(a[3]), "r"(b[0]), "r"(b[1]));
}

// ---------------- device scratch ----------------
// per-(b,co,h) width-pair extremes (max if gn_w*scale>=0 else min): [b][co][126][63]
__device__ float g_mw[(size_t)BATCH * COUT * HO * WP];
__device__ __align__(16) uint32_t g_w[9 * WTAP_U32];               // per-tap SW128 fp16
__device__ __align__(16) uint32_t g_xs[(size_t)BATCH * XS_PITCH * 32];  // pre-swizzled x fp16
__device__ float g_psum[BATCH * NGRP * NTILE];
__device__ float g_psq [BATCH * NGRP * NTILE];
__device__ float g_mean[BATCH * NGRP];
__device__ float g_rstd[BATCH * NGRP];

// ---------------------------------------------------------------------------
// Prep: conv_w (O,I,3,3) fp32 -> per-tap SW128 [co][k-word] fp16.
// word(co, kw) = co*32 + (kw ^ ((co&7)<<2))
// ---------------------------------------------------------------------------
__global__ void prep_kernel(const float* __restrict__ conv_w) {
    int idx = blockIdx.x * 256 + threadIdx.x;
    if (idx >= 9 * COUT * CIN) return;
    int r   = idx / (COUT * CIN);
    int rem = idx - r * (COUT * CIN);
    int co  = rem >> 6;
    int ci  = rem & 63;
    float w = conv_w[(co * CIN + ci) * 9 + r];
    __half h = __float2half_rn(w);
    uint32_t word = (uint32_t)(co * 32) + (((uint32_t)ci >> 1) ^ (uint32_t)((co & 7) << 2));
    unsigned short* gw = (unsigned short*)g_w;
    gw[(r * WTAP_U32 + word) * 2 + (ci & 1)] = *(unsigned short*)&h;
}

// ---------------------------------------------------------------------------
// Transpose/convert: x fp32 [b][ci][pos] -> g_xs fp16 swizzled [b][pos][word]
// storage word index w holds data word (w ^ ((pos&7)<<2)); data word c = ci pair.
// Tile: 64 pos x 64 ci per block. Coalesced reads and 128B-coalesced writes.
// ---------------------------------------------------------------------------
__global__ void xpose_kernel(const float* __restrict__ x) {
    __shared__ unsigned short st[64 * 66];   // [pos][ci], pitch 66 u16 (33 u32)
    const int t = threadIdx.x;               // 256 threads
    const int pos0 = blockIdx.x * 64;
    const int b    = blockIdx.y;
    const float* xb = x + (size_t)b * CIN * HWIN;

    for (int idx = t; idx < 64 * 16; idx += 256) {
        int ci = idx >> 4;
        int p4 = (idx & 15) << 2;
        float4 f = *(const float4*)(xb + (size_t)ci * HWIN + pos0 + p4);
        __half h0 = __float2half_rn(f.x);
        __half h1 = __float2half_rn(f.y);
        __half h2 = __float2half_rn(f.z);
        __half h3 = __float2half_rn(f.w);
        st[(p4 + 0) * 66 + ci] = *(unsigned short*)&h0;
        st[(p4 + 1) * 66 + ci] = *(unsigned short*)&h1;
        st[(p4 + 2) * 66 + ci] = *(unsigned short*)&h2;
        st[(p4 + 3) * 66 + ci] = *(unsigned short*)&h3;
    }
    __syncthreads();

    const uint32_t* st32 = (const uint32_t*)st;
    for (int idx = t; idx < 64 * 32; idx += 256) {
        int pos = idx >> 5;
        int w   = idx & 31;
        int ws  = w ^ ((pos & 7) << 2);      // data word stored at index w
        g_xs[((size_t)b * XS_PITCH + pos0 + pos) * 32 + w] = st32[pos * 33 + ws];
    }
}

// ---------------------------------------------------------------------------
// Conv via mma.sync m16n8k16 fp16 (single pass), fp32 acc.
// CTA = (row-pair i, batch b): M=256 pos x N=128 co x K=576.
// 512 threads, 16 warps: 8(M) x 2(N); warp tile 32x64.
// All 9 W taps + slab arrive via ONE cp.async group (slab pre-swizzled in g_xs)
// -> barrier-free mainloop, near-zero prologue.
// Epilogue: bias, GN partials, width-pair extreme -> g_mw (pool folded).
// ---------------------------------------------------------------------------
__global__ __launch_bounds__(NTHREADS, 1)
void conv_kernel(const float* __restrict__ conv_b,
                 const float* __restrict__ gn_w, const float* __restrict__ scale) {
    extern __shared__ char smem[];
    float*    sBias  = (float*)smem;
    float*    sRed   = (float*)(smem + 512);
    float*    sRedQ  = (float*)(smem + 1024);
    float*    sSgn   = (float*)(smem + 1536);
    uint32_t* sW     = (uint32_t*)(smem + SM_W);

    const int t    = threadIdx.x;
    const int wid  = t >> 5;
    const int lane = t & 31;
    const int g    = lane >> 2;
    const int tl   = lane & 3;
    const int li   = lane & 7;           // ldmatrix row-within-octet
    const int lsel = lane >> 3;          // ldmatrix matrix selector (0..3)
    const int wm   = wid & 7;            // M warp index (0..7)
    const int wn   = wid >> 3;           // N warp index (0..1)
    const int warp_m = wm * 32;
    const int warp_n = wn * 64;
    const int i  = blockIdx.x;           // row pair: output rows 2i, 2i+1
    const int b  = blockIdx.y;
    const int p0 = i * 256;

    const uint32_t sW_addr   = smem_u32(sW);
    const uint32_t slab_a    = smem_u32(smem + SM_SLAB);

    // ONE async group: all 9 W taps (144 KB) + x slab (65792 B, pre-swizzled)
    {
        const char* wsrc = (const char*)g_w;
        for (int j = t; j < WALL_B / 16; j += NTHREADS)
            CP_ASYNC16(sW_addr + j * 16, wsrc + j * 16);
        const char* xsrc = (const char*)(g_xs + ((size_t)b * XS_PITCH + p0) * 32);
        for (int j = t; j < SLAB_B / 16; j += NTHREADS)
            CP_ASYNC16(slab_a + j * 16, xsrc + j * 16);
        CP_COMMIT();
    }
    if (t < COUT) {
        sBias[t] = conv_b[t];
        sSgn[t]  = gn_w[t] * scale[t];
    }
    CP_WAIT0();
    __syncthreads();                     // the only barrier before the epilogue

    // B ldmatrix per-lane row constants
    uint32_t bRow[4]; int bKey[4];
#pragma unroll
    for (int np = 0; np < 4; np++) {
        int co = warp_n + ((2 * np + (lsel >> 1)) << 3) + li;
        bRow[np] = (uint32_t)(co * 128);
        bKey[np] = (co & 7) << 2;
    }
    const int bCh = (lsel & 1) << 2;     // chunk word add for B selector
    const int aCh = (lsel >> 1) << 2;    // chunk word add for A selector

    float acc[2][8][4];
#pragma unroll
    for (int m = 0; m < 2; m++)
#pragma unroll
        for (int n = 0; n < 8; n++)
#pragma unroll
            for (int e = 0; e < 4; e++) acc[m][n][e] = 0.f;

#pragma unroll
    for (int tap = 0; tap < 9; tap++) {
        const uint32_t WH_a = sW_addr + tap * WTAP_B;
        const int offp = (tap / 3) * 128 + (tap % 3);
        uint32_t aBase[2]; int aKey[2];
#pragma unroll
        for (int m = 0; m < 2; m++) {
            int row = offp + warp_m + m * 16 + ((lsel & 1) << 3) + li;
            aBase[m] = slab_a + (uint32_t)(row * 128);
            aKey[m]  = (row & 7) << 2;
        }
#pragma unroll
        for (int kc = 0; kc < 4; kc++) {
            const int kwA = kc * 8 + aCh;
            const int kwB = kc * 8 + bCh;
            uint32_t ah[2][4];
#pragma unroll
            for (int m = 0; m < 2; m++)
                LDMX4(ah[m], aBase[m] + (uint32_t)((kwA ^ aKey[m]) << 2));
#pragma unroll
            for (int np = 0; np < 4; np++) {
                const int n0 = 2 * np, n1 = n0 + 1;
                uint32_t bh[4];
                LDMX4(bh, WH_a + bRow[np] + (uint32_t)((kwB ^ bKey[np]) << 2));
#pragma unroll
                for (int m = 0; m < 2; m++) {
                    mma16816(acc[m][n0], ah[m], bh);
                    mma16816(acc[m][n1], ah[m], bh + 2);
                }
            }
        }
    }

    // ---- epilogue: bias, GN partials, width-pair extremes -> g_mw ----
    const bool gEven = ((g & 1) == 0);
#pragma unroll
    for (int n = 0; n < 8; n++) {
        const int co0 = warp_n + n * 8 + tl * 2;
        const int co1 = co0 + 1;
        const float b0 = sBias[co0];
        const float b1 = sBias[co1];
        const bool mx0 = (sSgn[co0] >= 0.f);
        const bool mx1 = (sSgn[co1] >= 0.f);
        float s = 0.f, q = 0.f;
#pragma unroll
        for (int m = 0; m < 2; m++) {
            const int pa = warp_m + m * 16 + g;
            const int pb = pa + 8;
            const int wA = pa & 127, hA = 2 * i + (pa >> 7);
            const int wB = pb & 127;
            float v0 = acc[m][n][0] + b0;
            float v1 = acc[m][n][1] + b1;
            float v2 = acc[m][n][2] + b0;
            float v3 = acc[m][n][3] + b1;
            // exchange with the adjacent-w lane (g ^ 1 -> lane ^ 4)
            float p0v = __shfl_xor_sync(0xffffffffu, v0, 4);
            float p1v = __shfl_xor_sync(0xffffffffu, v1, 4);
            float p2v = __shfl_xor_sync(0xffffffffu, v2, 4);
            float p3v = __shfl_xor_sync(0xffffffffu, v3, 4);
            if (wA < 126) { s += v0 + v1; q += v0 * v0 + v1 * v1; }
            if (wB < 126) { s += v2 + v3; q += v2 * v2 + v3 * v3; }
            if (gEven) {
                const size_t rowBase0 = ((size_t)(b * COUT + co0) * HO + hA) * WP;
                const size_t rowBase1 = ((size_t)(b * COUT + co1) * HO + hA) * WP;
                if (wA < 126) {
                    float e0 = mx0 ? fmaxf(v0, p0v) : fminf(v0, p0v);
                    float e1 = mx1 ? fmaxf(v1, p1v) : fminf(v1, p1v);
                    g_mw[rowBase0 + (wA >> 1)] = e0;
                    g_mw[rowBase1 + (wA >> 1)] = e1;
                }
                if (wB < 126) {
                    float e2 = mx0 ? fmaxf(v2, p2v) : fminf(v2, p2v);
                    float e3 = mx1 ? fmaxf(v3, p3v) : fminf(v3, p3v);
                    g_mw[rowBase0 + (wB >> 1)] = e2;
                    g_mw[rowBase1 + (wB >> 1)] = e3;
                }
            }
        }
#pragma unroll
        for (int o = 16; o > 0; o >>= 1) {
            s += __shfl_xor_sync(0xffffffffu, s, o);
            q += __shfl_xor_sync(0xffffffffu, q, o);
        }
        if (lane == 0) {
            sRed [(wn * 8 + n) * 8 + wm] = s;
            sRedQ[(wn * 8 + n) * 8 + wm] = q;
        }
    }
    __syncthreads();
    if (t < 16) {
        float S = 0.f, Q = 0.f;
#pragma unroll
        for (int k = 0; k < 8; k++) { S += sRed[t * 8 + k]; Q += sRedQ[t * 8 + k]; }
        g_psum[(b * NGRP + t) * NTILE + i] = S;
        g_psq [(b * NGRP + t) * NTILE + i] = Q;
    }
}

// ---------------------------------------------------------------------------
__global__ void stats_kernel() {
    int i = blockIdx.x * blockDim.x + threadIdx.x;
    if (i < BATCH * NGRP) {
        float s = 0.f, q = 0.f;
        const float* ps = g_psum + i * NTILE;
        const float* pq = g_psq  + i * NTILE;
        for (int tl = 0; tl < NTILE; tl++) { s += ps[tl]; q += pq[tl]; }
        const float invN = 1.f / (float)GN_N;
        float mean = s * invN;
        float var  = q * invN - mean * mean;
        g_mean[i] = mean;
        g_rstd[i] = rsqrtf(var + 1e-5f);
    }
}

// ---------------------------------------------------------------------------
// Pool: read 2 width-pair extremes (rows 2oh, 2oh+1), affine, max, clamp.
// ILP x2: each thread handles idx and idx + npool/2 (exactly divisible).
// ---------------------------------------------------------------------------
#define NPOOL (BATCH * COUT * HP * WP)
__global__ void pool_kernel(const float* __restrict__ gn_w,
                            const float* __restrict__ gn_b,
                            const float* __restrict__ scale,
                            float* __restrict__ out) {
    int idx = blockIdx.x * blockDim.x + threadIdx.x;
#pragma unroll
    for (int rep = 0; rep < 2; rep++, idx += NPOOL / 2) {
        int ow  = idx % WP;
        int tmp = idx / WP;
        int oh  = tmp % HP;
        tmp    /= HP;
        int c   = tmp % COUT;
        int b   = tmp / COUT;

        const int bg = b * NGRP + (c >> 3);
        const float mean = g_mean[bg];
        const float rstd = g_rstd[bg];
        const float a  = rstd * gn_w[c] * scale[c];
        const float bb = (gn_b[c] - mean * rstd * gn_w[c]) * scale[c];

        const float* mp = g_mw + ((size_t)(b * COUT + c) * HO + oh * 2) * (size_t)WP + ow;
        float v0 = fmaf(a, mp[0],  bb);
        float v1 = fmaf(a, mp[WP], bb);
        float m = fmaxf(v0, v1);
        out[idx] = fminf(fmaxf(m, 0.0f), 1.0f);
    }
}

// ---------------------------------------------------------------------------
extern "C" void kernel_launch(void* const* d_in, const int* in_sizes, int n_in,
                              void* d_out, int out_size) {
    const float* x      = (const float*)d_in[0];
    const float* conv_w = (const float*)d_in[1];
    const float* conv_b = (const float*)d_in[2];
    const float* gn_w   = (const float*)d_in[3];
    const float* gn_b   = (const float*)d_in[4];
    const float* scale  = (const float*)d_in[5];
    float* out = (float*)d_out;

    cudaFuncSetAttribute(conv_kernel, cudaFuncAttributeMaxDynamicSharedMemorySize, SMEM_TOTAL);

    prep_kernel<<<(9 * COUT * CIN + 255) / 256, 256>>>(conv_w);
    xpose_kernel<<<dim3(HWIN / 64, BATCH), 256>>>(x);
    conv_kernel<<<dim3(NTILE, BATCH), NTHREADS, SMEM_TOTAL>>>(conv_b, gn_w, scale);
    stats_kernel<<<2, 256>>>();
    pool_kernel<<<(NPOOL / 2 + 255) / 256, 256>>>(gn_w, gn_b, scale, out);
}

// round 16
// speedup vs baseline: 1.6460x; 1.0097x over previous
#include <cuda_runtime.h>
#include <cuda_fp16.h>
#include <cstdint>
#include <math.h>

// ---------------- problem constants ----------------
#define BATCH 32
#define CIN   64
#define HWIN  16384
#define COUT  128
#define HO    126
#define WO    126
#define NGRP  16
#define HP    63
#define WP    63
#define NTILE 63
#define GN_N  (8 * HO * WO)

// W tile per tap: SW128 layout [co][32 u32] fp16: 4096 u32 = 16 KB; all 9 resident
#define WTAP_U32 4096
#define WTAP_B   16384
#define WALL_B   (9 * WTAP_B)          // 147456

// slab: 514 pos x 32 u32 (SW128) fp16: 65792 B
#define SLAB_B   65792

// pre-swizzled fp16 x: [b][pos][32 u32], padded pitch (rows >=16384 stay zero)
#define XS_PITCH 16512

// smem layout (bytes):
//  [0,512)     bias (128 f)
//  [512,1024)  sRed (128 f)
//  [1024,1536) sRedQ (128 f)
//  [1536,2048) sSgn (128 f)
//  [2048,+147456)  W all taps
//  [149504,+65792) slab (reused as pool-exchange buffer in epilogue)
#define SM_W     2048
#define SM_SLAB  149504
#define SMEM_TOTAL 215296

#define NTHREADS 512

// ---------------- helpers ----------------
__device__ __forceinline__ uint32_t smem_u32(const void* p) {
    uint32_t a;
    asm("{ .reg .u64 t; cvta.to.shared.u64 t, %1; cvt.u32.u64 %0, t; }" : "=r"(a) : "l"(p));
    return a;
}
#define CP_ASYNC16(dst_u32, src_ptr) \
    asm volatile("cp.async.cg.shared.global [%0], [%1], 16;" :: "r"(dst_u32), "l"(src_ptr) : "memory")
#define CP_COMMIT() asm volatile("cp.async.commit_group;" ::: "memory")
#define CP_WAIT0()  asm volatile("cp.async.wait_group 0;" ::: "memory")

#define LDMX4(r, addr) \
    asm volatile("ldmatrix.sync.aligned.m8n8.x4.shared.b16 {%0,%1,%2,%3}, [%4];" \
        : "=r"((r)[0]), "=r"((r)[1]), "=r"((r)[2]), "=r"((r)[3]) : "r"(addr))

__device__ __forceinline__ void mma16816(float* c, const uint32_t* a, const uint32_t* b) {
    asm volatile(
        "mma.sync.aligned.m16n8k16.row.col.f32.f16.f16.f32 "
        "{%0,%1,%2,%3}, {%4,%5,%6,%7}, {%8,%9}, {%0,%1,%2,%3};"
        : "+f"(c[0]), "+f"(c[1]), "+f"(c[2]), "+f"(c[3])
        : "r"(a[0]), "r"(a[1]), "r"(a[2]), "r"(a[3]), "r"(b[0]), "r"(b[1]));
}

// ---------------- device scratch ----------------
// fully pooled pre-norm extremes, SAME layout as output: [b][co][63][63]
__device__ float g_mw[(size_t)BATCH * COUT * HP * WP];
__device__ __align__(16) uint32_t g_w[9 * WTAP_U32];               // per-tap SW128 fp16
__device__ __align__(16) uint32_t g_xs[(size_t)BATCH * XS_PITCH * 32];  // pre-swizzled x fp16
__device__ float g_psum[BATCH * NGRP * NTILE];
__device__ float g_psq [BATCH * NGRP * NTILE];
__device__ float g_mean[BATCH * NGRP];
__device__ float g_rstd[BATCH * NGRP];

// ---------------------------------------------------------------------------
// Prep: conv_w (O,I,3,3) fp32 -> per-tap SW128 [co][k-word] fp16.
// ---------------------------------------------------------------------------
__global__ void prep_kernel(const float* __restrict__ conv_w) {
    int idx = blockIdx.x * 256 + threadIdx.x;
    if (idx >= 9 * COUT * CIN) return;
    int r   = idx / (COUT * CIN);
    int rem = idx - r * (COUT * CIN);
    int co  = rem >> 6;
    int ci  = rem & 63;
    float w = conv_w[(co * CIN + ci) * 9 + r];
    __half h = __float2half_rn(w);
    uint32_t word = (uint32_t)(co * 32) + (((uint32_t)ci >> 1) ^ (uint32_t)((co & 7) << 2));
    unsigned short* gw = (unsigned short*)g_w;
    gw[(r * WTAP_U32 + word) * 2 + (ci & 1)] = *(unsigned short*)&h;
}

// ---------------------------------------------------------------------------
// Transpose/convert: x fp32 [b][ci][pos] -> g_xs fp16 swizzled [b][pos][word]
// ---------------------------------------------------------------------------
__global__ void xpose_kernel(const float* __restrict__ x) {
    __shared__ unsigned short st[64 * 66];   // [pos][ci], pitch 66 u16 (33 u32)
    const int t = threadIdx.x;               // 256 threads
    const int pos0 = blockIdx.x * 64;
    const int b    = blockIdx.y;
    const float* xb = x + (size_t)b * CIN * HWIN;

    for (int idx = t; idx < 64 * 16; idx += 256) {
        int ci = idx >> 4;
        int p4 = (idx & 15) << 2;
        float4 f = *(const float4*)(xb + (size_t)ci * HWIN + pos0 + p4);
        __half h0 = __float2half_rn(f.x);
        __half h1 = __float2half_rn(f.y);
        __half h2 = __float2half_rn(f.z);
        __half h3 = __float2half_rn(f.w);
        st[(p4 + 0) * 66 + ci] = *(unsigned short*)&h0;
        st[(p4 + 1) * 66 + ci] = *(unsigned short*)&h1;
        st[(p4 + 2) * 66 + ci] = *(unsigned short*)&h2;
        st[(p4 + 3) * 66 + ci] = *(unsigned short*)&h3;
    }
    __syncthreads();

    const uint32_t* st32 = (const uint32_t*)st;
    for (int idx = t; idx < 64 * 32; idx += 256) {
        int pos = idx >> 5;
        int w   = idx & 31;
        int ws  = w ^ ((pos & 7) << 2);      // data word stored at index w
        g_xs[((size_t)b * XS_PITCH + pos0 + pos) * 32 + w] = st32[pos * 33 + ws];
    }
}

// ---------------------------------------------------------------------------
// Conv via mma.sync m16n8k16 fp16 (single pass), fp32 acc.
// CTA = (row-pair i, batch b): M=256 pos x N=128 co x K=576.
// 512 threads, 16 warps: 8(M) x 2(N); warp tile 32x64.
// Epilogue: bias, GN partials, FULL 2x2 pool extreme -> g_mw.
//   Warps 0-3 hold row 2i, warps 4-7 hold row 2i+1 at identical widths:
//   pass1 stores row-2i width-pair extremes to smem (dead slab area),
//   pass2 (warps 4-7) combines for the height max and writes g_mw.
// ---------------------------------------------------------------------------
__global__ __launch_bounds__(NTHREADS, 1)
void conv_kernel(const float* __restrict__ conv_b,
                 const float* __restrict__ gn_w, const float* __restrict__ scale) {
    extern __shared__ char smem[];
    float*    sBias  = (float*)smem;
    float*    sRed   = (float*)(smem + 512);
    float*    sRedQ  = (float*)(smem + 1024);
    float*    sSgn   = (float*)(smem + 1536);
    uint32_t* sW     = (uint32_t*)(smem + SM_W);
    float*    sPool  = (float*)(smem + SM_SLAB);   // reused post-mainloop: [co][wp] 128*63 f

    const int t    = threadIdx.x;
    const int wid  = t >> 5;
    const int lane = t & 31;
    const int g    = lane >> 2;
    const int tl   = lane & 3;
    const int li   = lane & 7;           // ldmatrix row-within-octet
    const int lsel = lane >> 3;          // ldmatrix matrix selector (0..3)
    const int wm   = wid & 7;            // M warp index (0..7)
    const int wn   = wid >> 3;           // N warp index (0..1)
    const int warp_m = wm * 32;
    const int warp_n = wn * 64;
    const int i  = blockIdx.x;           // row pair: output rows 2i, 2i+1
    const int b  = blockIdx.y;
    const int p0 = i * 256;

    const uint32_t sW_addr = smem_u32(sW);
    const uint32_t slab_a  = smem_u32(smem + SM_SLAB);

    // ONE async group: all 9 W taps (144 KB) + x slab (65792 B, pre-swizzled)
    {
        const char* wsrc = (const char*)g_w;
        for (int j = t; j < WALL_B / 16; j += NTHREADS)
            CP_ASYNC16(sW_addr + j * 16, wsrc + j * 16);
        const char* xsrc = (const char*)(g_xs + ((size_t)b * XS_PITCH + p0) * 32);
        for (int j = t; j < SLAB_B / 16; j += NTHREADS)
            CP_ASYNC16(slab_a + j * 16, xsrc + j * 16);
        CP_COMMIT();
    }
    if (t < COUT) {
        sBias[t] = conv_b[t];
        sSgn[t]  = gn_w[t] * scale[t];
    }
    CP_WAIT0();
    __syncthreads();

    // B ldmatrix per-lane row constants
    uint32_t bRow[4]; int bKey[4];
#pragma unroll
    for (int np = 0; np < 4; np++) {
        int co = warp_n + ((2 * np + (lsel >> 1)) << 3) + li;
        bRow[np] = (uint32_t)(co * 128);
        bKey[np] = (co & 7) << 2;
    }
    const int bCh = (lsel & 1) << 2;     // chunk word add for B selector
    const int aCh = (lsel >> 1) << 2;    // chunk word add for A selector

    float acc[2][8][4];
#pragma unroll
    for (int m = 0; m < 2; m++)
#pragma unroll
        for (int n = 0; n < 8; n++)
#pragma unroll
            for (int e = 0; e < 4; e++) acc[m][n][e] = 0.f;

#pragma unroll
    for (int tap = 0; tap < 9; tap++) {
        const uint32_t WH_a = sW_addr + tap * WTAP_B;
        const int offp = (tap / 3) * 128 + (tap % 3);
        uint32_t aBase[2]; int aKey[2];
#pragma unroll
        for (int m = 0; m < 2; m++) {
            int row = offp + warp_m + m * 16 + ((lsel & 1) << 3) + li;
            aBase[m] = slab_a + (uint32_t)(row * 128);
            aKey[m]  = (row & 7) << 2;
        }
#pragma unroll
        for (int kc = 0; kc < 4; kc++) {
            const int kwA = kc * 8 + aCh;
            const int kwB = kc * 8 + bCh;
            uint32_t ah[2][4];
#pragma unroll
            for (int m = 0; m < 2; m++)
                LDMX4(ah[m], aBase[m] + (uint32_t)((kwA ^ aKey[m]) << 2));
#pragma unroll
            for (int np = 0; np < 4; np++) {
                const int n0 = 2 * np, n1 = n0 + 1;
                uint32_t bh[4];
                LDMX4(bh, WH_a + bRow[np] + (uint32_t)((kwB ^ bKey[np]) << 2));
#pragma unroll
                for (int m = 0; m < 2; m++) {
                    mma16816(acc[m][n0], ah[m], bh);
                    mma16816(acc[m][n1], ah[m], bh + 2);
                }
            }
        }
    }
    __syncthreads();                     // slab reads done; sPool reuse is safe

    // ---- epilogue pass 1: GN partials (all); row-2i extremes -> sPool (wm<4)
    const bool gEven = ((g & 1) == 0);
#pragma unroll
    for (int n = 0; n < 8; n++) {
        const int co0 = warp_n + n * 8 + tl * 2;
        const int co1 = co0 + 1;
        const float b0 = sBias[co0];
        const float b1 = sBias[co1];
        const bool mx0 = (sSgn[co0] >= 0.f);
        const bool mx1 = (sSgn[co1] >= 0.f);
        float s = 0.f, q = 0.f;
#pragma unroll
        for (int m = 0; m < 2; m++) {
            const int pa = warp_m + m * 16 + g;
            const int wA = pa & 127;
            const int wB = wA + 8;
            float v0 = acc[m][n][0] + b0;
            float v1 = acc[m][n][1] + b1;
            float v2 = acc[m][n][2] + b0;
            float v3 = acc[m][n][3] + b1;
            float p0v = __shfl_xor_sync(0xffffffffu, v0, 4);
            float p1v = __shfl_xor_sync(0xffffffffu, v1, 4);
            float p2v = __shfl_xor_sync(0xffffffffu, v2, 4);
            float p3v = __shfl_xor_sync(0xffffffffu, v3, 4);
            if (wA < 126) { s += v0 + v1; q += v0 * v0 + v1 * v1; }
            if (wB < 126) { s += v2 + v3; q += v2 * v2 + v3 * v3; }
            if (gEven && wm < 4) {       // row 2i: stash width-pair extremes
                if (wA < 126) {
                    sPool[co0 * WP + (wA >> 1)] = mx0 ? fmaxf(v0, p0v) : fminf(v0, p0v);
                    sPool[co1 * WP + (wA >> 1)] = mx1 ? fmaxf(v1, p1v) : fminf(v1, p1v);
                }
                if (wB < 126) {
                    sPool[co0 * WP + (wB >> 1)] = mx0 ? fmaxf(v2, p2v) : fminf(v2, p2v);
                    sPool[co1 * WP + (wB >> 1)] = mx1 ? fmaxf(v3, p3v) : fminf(v3, p3v);
                }
            }
        }
#pragma unroll
        for (int o = 16; o > 0; o >>= 1) {
            s += __shfl_xor_sync(0xffffffffu, s, o);
            q += __shfl_xor_sync(0xffffffffu, q, o);
        }
        if (lane == 0) {
            sRed [(wn * 8 + n) * 8 + wm] = s;
            sRedQ[(wn * 8 + n) * 8 + wm] = q;
        }
    }
    __syncthreads();

    // ---- epilogue pass 2 (wm>=4 = row 2i+1): combine height max, write g_mw
    if (wm >= 4) {
#pragma unroll
        for (int n = 0; n < 8; n++) {
            const int co0 = warp_n + n * 8 + tl * 2;
            const int co1 = co0 + 1;
            const float b0 = sBias[co0];
            const float b1 = sBias[co1];
            const bool mx0 = (sSgn[co0] >= 0.f);
            const bool mx1 = (sSgn[co1] >= 0.f);
#pragma unroll
            for (int m = 0; m < 2; m++) {
                const int pa = warp_m + m * 16 + g;
                const int wA = pa & 127;
                const int wB = wA + 8;
                float v0 = acc[m][n][0] + b0;
                float v1 = acc[m][n][1] + b1;
                float v2 = acc[m][n][2] + b0;
                float v3 = acc[m][n][3] + b1;
                float p0v = __shfl_xor_sync(0xffffffffu, v0, 4);
                float p1v = __shfl_xor_sync(0xffffffffu, v1, 4);
                float p2v = __shfl_xor_sync(0xffffffffu, v2, 4);
                float p3v = __shfl_xor_sync(0xffffffffu, v3, 4);
                if (gEven) {
                    const size_t out0 = ((size_t)(b * COUT + co0) * HP + i) * WP;
                    const size_t out1 = ((size_t)(b * COUT + co1) * HP + i) * WP;
                    if (wA < 126) {
                        float e0 = mx0 ? fmaxf(v0, p0v) : fminf(v0, p0v);
                        float e1 = mx1 ? fmaxf(v1, p1v) : fminf(v1, p1v);
                        float r0 = sPool[co0 * WP + (wA >> 1)];
                        float r1 = sPool[co1 * WP + (wA >> 1)];
                        g_mw[out0 + (wA >> 1)] = mx0 ? fmaxf(e0, r0) : fminf(e0, r0);
                        g_mw[out1 + (wA >> 1)] = mx1 ? fmaxf(e1, r1) : fminf(e1, r1);
                    }
                    if (wB < 126) {
                        float e2 = mx0 ? fmaxf(v2, p2v) : fminf(v2, p2v);
                        float e3 = mx1 ? fmaxf(v3, p3v) : fminf(v3, p3v);
                        float r2 = sPool[co0 * WP + (wB >> 1)];
                        float r3 = sPool[co1 * WP + (wB >> 1)];
                        g_mw[out0 + (wB >> 1)] = mx0 ? fmaxf(e2, r2) : fminf(e2, r2);
                        g_mw[out1 + (wB >> 1)] = mx1 ? fmaxf(e3, r3) : fminf(e3, r3);
                    }
                }
            }
        }
    }
    if (t < 16) {
        float S = 0.f, Q = 0.f;
#pragma unroll
        for (int k = 0; k < 8; k++) { S += sRed[t * 8 + k]; Q += sRedQ[t * 8 + k]; }
        g_psum[(b * NGRP + t) * NTILE + i] = S;
        g_psq [(b * NGRP + t) * NTILE + i] = Q;
    }
}

// ---------------------------------------------------------------------------
// Stats: one warp per (b,g); lane-parallel partial loads + shfl reduce.
// ---------------------------------------------------------------------------
__global__ void stats_kernel() {
    const int w = (blockIdx.x * blockDim.x + threadIdx.x) >> 5;   // 0..511
    const int lane = threadIdx.x & 31;
    if (w >= BATCH * NGRP) return;
    const float* ps = g_psum + w * NTILE;
    const float* pq = g_psq  + w * NTILE;
    float s = ps[lane], q = pq[lane];
    if (lane < NTILE - 32) { s += ps[lane + 32]; q += pq[lane + 32]; }
#pragma unroll
    for (int o = 16; o > 0; o >>= 1) {
        s += __shfl_xor_sync(0xffffffffu, s, o);
        q += __shfl_xor_sync(0xffffffffu, q, o);
    }
    if (lane == 0) {
        const float invN = 1.f / (float)GN_N;
        float mean = s * invN;
        float var  = q * invN - mean * mean;
        g_mean[w] = mean;
        g_rstd[w] = rsqrtf(var + 1e-5f);
    }
}

// ---------------------------------------------------------------------------
// Pool: pure streaming — g_mw already holds pooled pre-norm extremes in the
// output layout. out = clip(a * mw + bb).
// ---------------------------------------------------------------------------
#define NPOOL (BATCH * COUT * HP * WP)
__global__ void pool_kernel(const float* __restrict__ gn_w,
                            const float* __restrict__ gn_b,
                            const float* __restrict__ scale,
                            float* __restrict__ out) {
    int idx = blockIdx.x * blockDim.x + threadIdx.x;
#pragma unroll
    for (int rep = 0; rep < 2; rep++, idx += NPOOL / 2) {
        int c = (idx / (HP * WP)) % COUT;
        int bg = (idx / (COUT * HP * WP)) * NGRP + (c >> 3);
        const float mean = g_mean[bg];
        const float rstd = g_rstd[bg];
        const float a  = rstd * gn_w[c] * scale[c];
        const float bb = (gn_b[c] - mean * rstd * gn_w[c]) * scale[c];
        float v = fmaf(a, g_mw[idx], bb);
        out[idx] = fminf(fmaxf(v, 0.0f), 1.0f);
    }
}

// ---------------------------------------------------------------------------
extern "C" void kernel_launch(void* const* d_in, const int* in_sizes, int n_in,
                              void* d_out, int out_size) {
    const float* x      = (const float*)d_in[0];
    const float* conv_w = (const float*)d_in[1];
    const float* conv_b = (const float*)d_in[2];
    const float* gn_w   = (const float*)d_in[3];
    const float* gn_b   = (const float*)d_in[4];
    const float* scale  = (const float*)d_in[5];
    float* out = (float*)d_out;

    cudaFuncSetAttribute(conv_kernel, cudaFuncAttributeMaxDynamicSharedMemorySize, SMEM_TOTAL);

    prep_kernel<<<(9 * COUT * CIN + 255) / 256, 256>>>(conv_w);
    xpose_kernel<<<dim3(HWIN / 64, BATCH), 256>>>(x);
    conv_kernel<<<dim3(NTILE, BATCH), NTHREADS, SMEM_TOTAL>>>(conv_b, gn_w, scale);
    stats_kernel<<<64, 256>>>();
    pool_kernel<<<(NPOOL / 2 + 255) / 256, 256>>>(gn_w, gn_b, scale, out);
}

// round 17
// speedup vs baseline: 1.7363x; 1.0549x over previous
#include <cuda_runtime.h>
#include <cuda_fp16.h>
#include <cstdint>
#include <math.h>

// ---------------- problem constants ----------------
#define BATCH 32
#define CIN   64
#define HWIN  16384
#define COUT  128
#define HO    126
#define WO    126
#define NGRP  16
#define HP    63
#define WP    63
#define NTILE 63
#define GN_N  (8 * HO * WO)

// W tile per tap: SW128 layout [co][32 u32] fp16: 4096 u32 = 16 KB; all 9 resident
#define WTAP_U32 4096
#define WTAP_B   16384
#define WALL_B   (9 * WTAP_B)          // 147456

// slab: 514 pos x 32 u32 (SW128) fp16: 65792 B
#define SLAB_B   65792

// pre-swizzled fp16 x: [b][pos][32 u32], padded pitch (rows >=16384 stay zero)
#define XS_PITCH 16512

// smem layout (bytes):
//  [0,512)     bias (128 f)
//  [512,1024)  sRed (128 f)
//  [1024,1536) sRedQ (128 f)
//  [1536,2048) sSgn (128 f)
//  [2048,+147456)  W all taps
//  [149504,+65792) slab (reused as pool-exchange buffer in epilogue)
#define SM_W     2048
#define SM_SLAB  149504
#define SMEM_TOTAL 215296

#define NTHREADS 512

// ---------------- helpers ----------------
__device__ __forceinline__ uint32_t smem_u32(const void* p) {
    uint32_t a;
    asm("{ .reg .u64 t; cvta.to.shared.u64 t, %1; cvt.u32.u64 %0, t; }" : "=r"(a) : "l"(p));
    return a;
}
#define CP_ASYNC16(dst_u32, src_ptr) \
    asm volatile("cp.async.cg.shared.global [%0], [%1], 16;" :: "r"(dst_u32), "l"(src_ptr) : "memory")
#define CP_COMMIT() asm volatile("cp.async.commit_group;" ::: "memory")

#define LDMX4(r, addr) \
    asm volatile("ldmatrix.sync.aligned.m8n8.x4.shared.b16 {%0,%1,%2,%3}, [%4];" \
        : "=r"((r)[0]), "=r"((r)[1]), "=r"((r)[2]), "=r"((r)[3]) : "r"(addr))

__device__ __forceinline__ void mma16816(float* c, const uint32_t* a, const uint32_t* b) {
    asm volatile(
        "mma.sync.aligned.m16n8k16.row.col.f32.f16.f16.f32 "
        "{%0,%1,%2,%3}, {%4,%5,%6,%7}, {%8,%9}, {%0,%1,%2,%3};"
        : "+f"(c[0]), "+f"(c[1]), "+f"(c[2]), "+f"(c[3])
        : "r"(a[0]), "r"(a[1]), "r"(a[2]), "r"(a[3]), "r"(b[0]), "r"(b[1]));
}

// ---------------- device scratch ----------------
// fully pooled pre-norm extremes, SAME layout as output: [b][co][63][63]
__device__ __align__(16) float g_mw[(size_t)BATCH * COUT * HP * WP];
__device__ __align__(16) uint32_t g_w[9 * WTAP_U32];               // per-tap SW128 fp16
__device__ __align__(16) uint32_t g_xs[(size_t)BATCH * XS_PITCH * 32];  // pre-swizzled x fp16
__device__ float g_psum[BATCH * NGRP * NTILE];
__device__ float g_psq [BATCH * NGRP * NTILE];
__device__ float g_a [BATCH * COUT];     // per-(b,c) affine mult
__device__ float g_bb[BATCH * COUT];     // per-(b,c) affine add

// ---------------------------------------------------------------------------
// Prep: conv_w (O,I,3,3) fp32 -> per-tap SW128 [co][k-word] fp16.
// ---------------------------------------------------------------------------
__global__ void prep_kernel(const float* __restrict__ conv_w) {
    int idx = blockIdx.x * 256 + threadIdx.x;
    if (idx >= 9 * COUT * CIN) return;
    int r   = idx / (COUT * CIN);
    int rem = idx - r * (COUT * CIN);
    int co  = rem >> 6;
    int ci  = rem & 63;
    float w = conv_w[(co * CIN + ci) * 9 + r];
    __half h = __float2half_rn(w);
    uint32_t word = (uint32_t)(co * 32) + (((uint32_t)ci >> 1) ^ (uint32_t)((co & 7) << 2));
    unsigned short* gw = (unsigned short*)g_w;
    gw[(r * WTAP_U32 + word) * 2 + (ci & 1)] = *(unsigned short*)&h;
}

// ---------------------------------------------------------------------------
// Transpose/convert: x fp32 [b][ci][pos] -> g_xs fp16 swizzled [b][pos][word]
// ---------------------------------------------------------------------------
__global__ void xpose_kernel(const float* __restrict__ x) {
    __shared__ unsigned short st[64 * 66];   // [pos][ci], pitch 66 u16 (33 u32)
    const int t = threadIdx.x;               // 256 threads
    const int pos0 = blockIdx.x * 64;
    const int b    = blockIdx.y;
    const float* xb = x + (size_t)b * CIN * HWIN;

    for (int idx = t; idx < 64 * 16; idx += 256) {
        int ci = idx >> 4;
        int p4 = (idx & 15) << 2;
        float4 f = *(const float4*)(xb + (size_t)ci * HWIN + pos0 + p4);
        __half h0 = __float2half_rn(f.x);
        __half h1 = __float2half_rn(f.y);
        __half h2 = __float2half_rn(f.z);
        __half h3 = __float2half_rn(f.w);
        st[(p4 + 0) * 66 + ci] = *(unsigned short*)&h0;
        st[(p4 + 1) * 66 + ci] = *(unsigned short*)&h1;
        st[(p4 + 2) * 66 + ci] = *(unsigned short*)&h2;
        st[(p4 + 3) * 66 + ci] = *(unsigned short*)&h3;
    }
    __syncthreads();

    const uint32_t* st32 = (const uint32_t*)st;
    for (int idx = t; idx < 64 * 32; idx += 256) {
        int pos = idx >> 5;
        int w   = idx & 31;
        int ws  = w ^ ((pos & 7) << 2);      // data word stored at index w
        g_xs[((size_t)b * XS_PITCH + pos0 + pos) * 32 + w] = st32[pos * 33 + ws];
    }
}

// ---------------------------------------------------------------------------
// Conv via mma.sync m16n8k16 fp16 (single pass), fp32 acc.
// CTA = (row-pair i, batch b): M=256 pos x N=128 co x K=576.
// 512 threads, 16 warps: 8(M) x 2(N); warp tile 32x64.
// STAGED prologue: group0 = slab + W tap0; groups 1..8 = W taps 1..8.
// Mainloop waits wait_group(8-tap) per tap -> MMAs start after 82 KB,
// remaining W streams behind the tensor pipe.
// Epilogue: bias, GN partials, FULL 2x2 pool extreme -> g_mw.
// ---------------------------------------------------------------------------
__global__ __launch_bounds__(NTHREADS, 1)
void conv_kernel(const float* __restrict__ conv_b,
                 const float* __restrict__ gn_w, const float* __restrict__ scale) {
    extern __shared__ char smem[];
    float*    sBias  = (float*)smem;
    float*    sRed   = (float*)(smem + 512);
    float*    sRedQ  = (float*)(smem + 1024);
    float*    sSgn   = (float*)(smem + 1536);
    uint32_t* sW     = (uint32_t*)(smem + SM_W);
    float*    sPool  = (float*)(smem + SM_SLAB);   // reused post-mainloop: [co][wp]

    const int t    = threadIdx.x;
    const int wid  = t >> 5;
    const int lane = t & 31;
    const int g    = lane >> 2;
    const int tl   = lane & 3;
    const int li   = lane & 7;           // ldmatrix row-within-octet
    const int lsel = lane >> 3;          // ldmatrix matrix selector (0..3)
    const int wm   = wid & 7;            // M warp index (0..7)
    const int wn   = wid >> 3;           // N warp index (0..1)
    const int warp_m = wm * 32;
    const int warp_n = wn * 64;
    const int i  = blockIdx.x;           // row pair: output rows 2i, 2i+1
    const int b  = blockIdx.y;
    const int p0 = i * 256;

    const uint32_t sW_addr = smem_u32(sW);
    const uint32_t slab_a  = smem_u32(smem + SM_SLAB);

    // ---- group 0: x slab + W tap 0 ----
    {
        const char* xsrc = (const char*)(g_xs + ((size_t)b * XS_PITCH + p0) * 32);
        for (int j = t; j < SLAB_B / 16; j += NTHREADS)
            CP_ASYNC16(slab_a + j * 16, xsrc + j * 16);
        const char* wsrc = (const char*)g_w;
        for (int j = t; j < WTAP_B / 16; j += NTHREADS)
            CP_ASYNC16(sW_addr + j * 16, wsrc + j * 16);
        CP_COMMIT();
    }
    // ---- groups 1..8: W taps 1..8 ----
#pragma unroll
    for (int tp = 1; tp < 9; tp++) {
        const char* wsrc = (const char*)(g_w + tp * WTAP_U32);
        const uint32_t dst = sW_addr + tp * WTAP_B;
        for (int j = t; j < WTAP_B / 16; j += NTHREADS)
            CP_ASYNC16(dst + j * 16, wsrc + j * 16);
        CP_COMMIT();
    }
    if (t < COUT) {
        sBias[t] = conv_b[t];
        sSgn[t]  = gn_w[t] * scale[t];
    }

    // B ldmatrix per-lane row constants
    uint32_t bRow[4]; int bKey[4];
#pragma unroll
    for (int np = 0; np < 4; np++) {
        int co = warp_n + ((2 * np + (lsel >> 1)) << 3) + li;
        bRow[np] = (uint32_t)(co * 128);
        bKey[np] = (co & 7) << 2;
    }
    const int bCh = (lsel & 1) << 2;     // chunk word add for B selector
    const int aCh = (lsel >> 1) << 2;    // chunk word add for A selector

    float acc[2][8][4];
#pragma unroll
    for (int m = 0; m < 2; m++)
#pragma unroll
        for (int n = 0; n < 8; n++)
#pragma unroll
            for (int e = 0; e < 4; e++) acc[m][n][e] = 0.f;

#pragma unroll
    for (int tap = 0; tap < 9; tap++) {
        // wait for group `tap` (slab+W0 for tap 0), then make smem visible
        switch (tap) {
            case 0: asm volatile("cp.async.wait_group 8;" ::: "memory"); break;
            case 1: asm volatile("cp.async.wait_group 7;" ::: "memory"); break;
            case 2: asm volatile("cp.async.wait_group 6;" ::: "memory"); break;
            case 3: asm volatile("cp.async.wait_group 5;" ::: "memory"); break;
            case 4: asm volatile("cp.async.wait_group 4;" ::: "memory"); break;
            case 5: asm volatile("cp.async.wait_group 3;" ::: "memory"); break;
            case 6: asm volatile("cp.async.wait_group 2;" ::: "memory"); break;
            case 7: asm volatile("cp.async.wait_group 1;" ::: "memory"); break;
            default: asm volatile("cp.async.wait_group 0;" ::: "memory"); break;
        }
        __syncthreads();

        const uint32_t WH_a = sW_addr + tap * WTAP_B;
        const int offp = (tap / 3) * 128 + (tap % 3);
        uint32_t aBase[2]; int aKey[2];
#pragma unroll
        for (int m = 0; m < 2; m++) {
            int row = offp + warp_m + m * 16 + ((lsel & 1) << 3) + li;
            aBase[m] = slab_a + (uint32_t)(row * 128);
            aKey[m]  = (row & 7) << 2;
        }
#pragma unroll
        for (int kc = 0; kc < 4; kc++) {
            const int kwA = kc * 8 + aCh;
            const int kwB = kc * 8 + bCh;
            uint32_t ah[2][4];
#pragma unroll
            for (int m = 0; m < 2; m++)
                LDMX4(ah[m], aBase[m] + (uint32_t)((kwA ^ aKey[m]) << 2));
#pragma unroll
            for (int np = 0; np < 4; np++) {
                const int n0 = 2 * np, n1 = n0 + 1;
                uint32_t bh[4];
                LDMX4(bh, WH_a + bRow[np] + (uint32_t)((kwB ^ bKey[np]) << 2));
#pragma unroll
                for (int m = 0; m < 2; m++) {
                    mma16816(acc[m][n0], ah[m], bh);
                    mma16816(acc[m][n1], ah[m], bh + 2);
                }
            }
        }
    }
    __syncthreads();                     // slab reads done; sPool reuse is safe

    // ---- epilogue pass 1: GN partials (all); row-2i extremes -> sPool (wm<4)
    const bool gEven = ((g & 1) == 0);
#pragma unroll
    for (int n = 0; n < 8; n++) {
        const int co0 = warp_n + n * 8 + tl * 2;
        const int co1 = co0 + 1;
        const float b0 = sBias[co0];
        const float b1 = sBias[co1];
        const bool mx0 = (sSgn[co0] >= 0.f);
        const bool mx1 = (sSgn[co1] >= 0.f);
        float s = 0.f, q = 0.f;
#pragma unroll
        for (int m = 0; m < 2; m++) {
            const int pa = warp_m + m * 16 + g;
            const int wA = pa & 127;
            const int wB = wA + 8;
            float v0 = acc[m][n][0] + b0;
            float v1 = acc[m][n][1] + b1;
            float v2 = acc[m][n][2] + b0;
            float v3 = acc[m][n][3] + b1;
            float p0v = __shfl_xor_sync(0xffffffffu, v0, 4);
            float p1v = __shfl_xor_sync(0xffffffffu, v1, 4);
            float p2v = __shfl_xor_sync(0xffffffffu, v2, 4);
            float p3v = __shfl_xor_sync(0xffffffffu, v3, 4);
            if (wA < 126) { s += v0 + v1; q += v0 * v0 + v1 * v1; }
            if (wB < 126) { s += v2 + v3; q += v2 * v2 + v3 * v3; }
            if (gEven && wm < 4) {       // row 2i: stash width-pair extremes
                if (wA < 126) {
                    sPool[co0 * WP + (wA >> 1)] = mx0 ? fmaxf(v0, p0v) : fminf(v0, p0v);
                    sPool[co1 * WP + (wA >> 1)] = mx1 ? fmaxf(v1, p1v) : fminf(v1, p1v);
                }
                if (wB < 126) {
                    sPool[co0 * WP + (wB >> 1)] = mx0 ? fmaxf(v2, p2v) : fminf(v2, p2v);
                    sPool[co1 * WP + (wB >> 1)] = mx1 ? fmaxf(v3, p3v) : fminf(v3, p3v);
                }
            }
        }
#pragma unroll
        for (int o = 16; o > 0; o >>= 1) {
            s += __shfl_xor_sync(0xffffffffu, s, o);
            q += __shfl_xor_sync(0xffffffffu, q, o);
        }
        if (lane == 0) {
            sRed [(wn * 8 + n) * 8 + wm] = s;
            sRedQ[(wn * 8 + n) * 8 + wm] = q;
        }
    }
    __syncthreads();

    // ---- epilogue pass 2 (wm>=4 = row 2i+1): combine height max, write g_mw
    if (wm >= 4) {
#pragma unroll
        for (int n = 0; n < 8; n++) {
            const int co0 = warp_n + n * 8 + tl * 2;
            const int co1 = co0 + 1;
            const float b0 = sBias[co0];
            const float b1 = sBias[co1];
            const bool mx0 = (sSgn[co0] >= 0.f);
            const bool mx1 = (sSgn[co1] >= 0.f);
#pragma unroll
            for (int m = 0; m < 2; m++) {
                const int pa = warp_m + m * 16 + g;
                const int wA = pa & 127;
                const int wB = wA + 8;
                float v0 = acc[m][n][0] + b0;
                float v1 = acc[m][n][1] + b1;
                float v2 = acc[m][n][2] + b0;
                float v3 = acc[m][n][3] + b1;
                float p0v = __shfl_xor_sync(0xffffffffu, v0, 4);
                float p1v = __shfl_xor_sync(0xffffffffu, v1, 4);
                float p2v = __shfl_xor_sync(0xffffffffu, v2, 4);
                float p3v = __shfl_xor_sync(0xffffffffu, v3, 4);
                if (gEven) {
                    const size_t out0 = ((size_t)(b * COUT + co0) * HP + i) * WP;
                    const size_t out1 = ((size_t)(b * COUT + co1) * HP + i) * WP;
                    if (wA < 126) {
                        float e0 = mx0 ? fmaxf(v0, p0v) : fminf(v0, p0v);
                        float e1 = mx1 ? fmaxf(v1, p1v) : fminf(v1, p1v);
                        float r0 = sPool[co0 * WP + (wA >> 1)];
                        float r1 = sPool[co1 * WP + (wA >> 1)];
                        g_mw[out0 + (wA >> 1)] = mx0 ? fmaxf(e0, r0) : fminf(e0, r0);
                        g_mw[out1 + (wA >> 1)] = mx1 ? fmaxf(e1, r1) : fminf(e1, r1);
                    }
                    if (wB < 126) {
                        float e2 = mx0 ? fmaxf(v2, p2v) : fminf(v2, p2v);
                        float e3 = mx1 ? fmaxf(v3, p3v) : fminf(v3, p3v);
                        float r2 = sPool[co0 * WP + (wB >> 1)];
                        float r3 = sPool[co1 * WP + (wB >> 1)];
                        g_mw[out0 + (wB >> 1)] = mx0 ? fmaxf(e2, r2) : fminf(e2, r2);
                        g_mw[out1 + (wB >> 1)] = mx1 ? fmaxf(e3, r3) : fminf(e3, r3);
                    }
                }
            }
        }
    }
    if (t < 16) {
        float S = 0.f, Q = 0.f;
#pragma unroll
        for (int k = 0; k < 8; k++) { S += sRed[t * 8 + k]; Q += sRedQ[t * 8 + k]; }
        g_psum[(b * NGRP + t) * NTILE + i] = S;
        g_psq [(b * NGRP + t) * NTILE + i] = Q;
    }
}

// ---------------------------------------------------------------------------
// Stats: one warp per (b,g); lane-parallel loads + shfl reduce.
// Also emits per-(b,c) affine constants a, bb (lanes 0..7).
// ---------------------------------------------------------------------------
__global__ void stats_kernel(const float* __restrict__ gn_w,
                             const float* __restrict__ gn_b,
                             const float* __restrict__ scale) {
    const int w = (blockIdx.x * blockDim.x + threadIdx.x) >> 5;   // 0..511
    const int lane = threadIdx.x & 31;
    if (w >= BATCH * NGRP) return;
    const float* ps = g_psum + w * NTILE;
    const float* pq = g_psq  + w * NTILE;
    float s = ps[lane], q = pq[lane];
    if (lane < NTILE - 32) { s += ps[lane + 32]; q += pq[lane + 32]; }
#pragma unroll
    for (int o = 16; o > 0; o >>= 1) {
        s += __shfl_xor_sync(0xffffffffu, s, o);
        q += __shfl_xor_sync(0xffffffffu, q, o);
    }
    const float invN = 1.f / (float)GN_N;
    float mean = __shfl_sync(0xffffffffu, s, 0) * invN;
    float var  = __shfl_sync(0xffffffffu, q, 0) * invN - mean * mean;
    float rstd = rsqrtf(var + 1e-5f);
    if (lane < 8) {
        const int b = w >> 4;            // w = b*NGRP + g
        const int gidx = w & 15;
        const int c = gidx * 8 + lane;
        const int bc = b * COUT + c;
        g_a [bc] = rstd * gn_w[c] * scale[c];
        g_bb[bc] = (gn_b[c] - mean * rstd * gn_w[c]) * scale[c];
    }
}

// ---------------------------------------------------------------------------
// Pool: pure float4 stream — out = clip(a * mw + bb), affine precomputed.
// ---------------------------------------------------------------------------
#define NPOOL (BATCH * COUT * HP * WP)
__global__ void pool_kernel(float* __restrict__ out) {
    const int i4 = blockIdx.x * blockDim.x + threadIdx.x;   // NPOOL/4 = 4064256 exact
    float4 m = ((const float4*)g_mw)[i4];
    const int base = i4 * 4;
    float r[4];
    const float* mv = &m.x;
#pragma unroll
    for (int e = 0; e < 4; e++) {
        int cc = (base + e) / (HP * WP);        // = b*COUT + c
        float v = fmaf(g_a[cc], mv[e], g_bb[cc]);
        r[e] = fminf(fmaxf(v, 0.0f), 1.0f);
    }
    ((float4*)out)[i4] = make_float4(r[0], r[1], r[2], r[3]);
}

// ---------------------------------------------------------------------------
extern "C" void kernel_launch(void* const* d_in, const int* in_sizes, int n_in,
                              void* d_out, int out_size) {
    const float* x      = (const float*)d_in[0];
    const float* conv_w = (const float*)d_in[1];
    const float* conv_b = (const float*)d_in[2];
    const float* gn_w   = (const float*)d_in[3];
    const float* gn_b   = (const float*)d_in[4];
    const float* scale  = (const float*)d_in[5];
    float* out = (float*)d_out;

    cudaFuncSetAttribute(conv_kernel, cudaFuncAttributeMaxDynamicSharedMemorySize, SMEM_TOTAL);

    prep_kernel<<<(9 * COUT * CIN + 255) / 256, 256>>>(conv_w);
    xpose_kernel<<<dim3(HWIN / 64, BATCH), 256>>>(x);
    conv_kernel<<<dim3(NTILE, BATCH), NTHREADS, SMEM_TOTAL>>>(conv_b, gn_w, scale);
    stats_kernel<<<64, 256>>>(gn_w, gn_b, scale);
    pool_kernel<<<NPOOL / 4 / 256, 256>>>(out);
}